// round 2
// baseline (speedup 1.0000x reference)
#include <cuda_runtime.h>
#include <cuda_bf16.h>

// Problem constants
#define BB   8
#define CIN  8
#define COUT 16
#define HW   65536        // 256*256
#define HW2  32768        // HW/2 (float2 vectors per image plane)

// Per-(o,j) parameters: {center, a} with a = -log2(e) / (2*w^2)
// so that exp(-(x-c)^2/(2w^2)) = ex2( (x-c)^2 * a ).
__device__ float2 g_params[COUT * CIN];

__device__ __forceinline__ float ex2f(float v) {
    float r;
    asm("ex2.approx.f32 %0, %1;" : "=f"(r) : "f"(v));
    return r;
}

__global__ void prep_params_kernel(const float* __restrict__ centers,
                                   const float* __restrict__ widths) {
    int i = threadIdx.x;
    if (i < COUT * CIN) {
        float w = widths[i];
        // a = -log2(e) / (2 w^2)
        float a = -1.4426950408889634f / (2.0f * w * w);
        g_params[i] = make_float2(centers[i], a);
    }
}

__global__ __launch_bounds__(256) void soft_hist_kernel(
    const float2* __restrict__ x,   // [B][CIN][HW2] as float2
    float2* __restrict__ out)       // [B][COUT][HW2] as float2
{
    __shared__ float2 sp[COUT * CIN];
    int t = threadIdx.x;
    if (t < COUT * CIN) sp[t] = g_params[t];
    __syncthreads();

    int gv = blockIdx.x * blockDim.x + t;       // vector index in [0, B*HW2)
    int b    = gv >> 15;                        // gv / HW2
    int pos2 = gv & (HW2 - 1);                  // gv % HW2

    // Load the 8 input-channel values for this spatial pair (independent LDGs, MLP=8)
    const float2* xin = x + (size_t)b * CIN * HW2 + pos2;
    float2 xv[CIN];
    #pragma unroll
    for (int j = 0; j < CIN; j++) xv[j] = xin[(size_t)j * HW2];

    float2* op = out + (size_t)b * COUT * HW2 + pos2;

    #pragma unroll
    for (int o = 0; o < COUT; o++) {
        float s0 = 0.0f, s1 = 0.0f;
        #pragma unroll
        for (int j = 0; j < CIN; j++) {
            float2 p = sp[o * CIN + j];         // broadcast LDS.64
            float t0 = xv[j].x - p.x;
            float t1 = xv[j].y - p.x;
            // factored form (t*a)*t keeps accuracy when |a| is large
            s0 += ex2f((t0 * p.y) * t0);
            s1 += ex2f((t1 * p.y) * t1);
        }
        op[(size_t)o * HW2] = make_float2(s0, s1);
    }
}

extern "C" void kernel_launch(void* const* d_in, const int* in_sizes, int n_in,
                              void* d_out, int out_size) {
    const float* x       = (const float*)d_in[0];   // [8,8,256,256]
    const float* centers = (const float*)d_in[1];   // [16,8]
    const float* widths  = (const float*)d_in[2];   // [16,8]
    float* out = (float*)d_out;                     // [8,16,256,256]

    prep_params_kernel<<<1, 128>>>(centers, widths);

    const int total_vec = BB * HW2;                 // 262144
    const int block = 256;
    const int grid  = total_vec / block;            // 1024
    soft_hist_kernel<<<grid, block>>>((const float2*)x, (float2*)out);
}

// round 5
// speedup vs baseline: 1.1099x; 1.1099x over previous
#include <cuda_runtime.h>
#include <cuda_bf16.h>

// Problem constants
#define BB   8
#define CIN  8
#define COUT 16
#define HW   65536        // 256*256
#define HW2  32768        // HW/2 (float2 vectors per image plane)
#define NPAR (COUT * CIN) // 128

__device__ __forceinline__ float ex2f(float v) {
    float r;
    asm("ex2.approx.f32 %0, %1;" : "=f"(r) : "f"(v));
    return r;
}

// exp(-(x-c)^2/(2w^2)) = ex2( A*x^2 + B*x + D )
//   A = -log2(e)/(2w^2),  B = -2*A*c... (wait: expand a(x-c)^2 = a x^2 -2ac x + a c^2)
//   A = a, B = -2ac, D = a c^2, with a = -log2(e)/(2w^2)
__global__ __launch_bounds__(256) void soft_hist_kernel(
    const float2* __restrict__ x,          // [B][CIN][HW2] as float2
    const float*  __restrict__ centers,    // [COUT][CIN]
    const float*  __restrict__ widths,     // [COUT][CIN]
    float2* __restrict__ out)              // [B][COUT][HW2] as float2
{
    __shared__ float4 sp[NPAR];
    int t = threadIdx.x;
    if (t < NPAR) {
        float c = centers[t];
        float w = widths[t];
        float a = -0.72134752044448170f / (w * w);   // -log2(e)/2 / w^2
        sp[t] = make_float4(a, -2.0f * a * c, a * c * c, 0.0f);
    }
    __syncthreads();

    int gv   = blockIdx.x * blockDim.x + t;     // vector index in [0, B*HW2)
    int b    = gv >> 15;                        // gv / HW2
    int pos2 = gv & (HW2 - 1);                  // gv % HW2

    // Load the 8 input-channel values for this spatial pair (independent LDGs)
    const float2* xin = x + (size_t)b * CIN * HW2 + pos2;
    float2 xv[CIN];
    #pragma unroll
    for (int j = 0; j < CIN; j++) xv[j] = xin[(size_t)j * HW2];

    // Hoist x^2 (reused across all 16 output channels)
    float2 xs[CIN];
    #pragma unroll
    for (int j = 0; j < CIN; j++)
        xs[j] = make_float2(xv[j].x * xv[j].x, xv[j].y * xv[j].y);

    float2* op = out + (size_t)b * COUT * HW2 + pos2;

    #pragma unroll
    for (int o = 0; o < COUT; o++) {
        float s0 = 0.0f, s1 = 0.0f;
        #pragma unroll
        for (int j = 0; j < CIN; j++) {
            float4 p = sp[o * CIN + j];          // broadcast LDS.128
            // arg = A*x^2 + B*x + D  (2 FFMA per position)
            float a0 = fmaf(p.x, xs[j].x, fmaf(p.y, xv[j].x, p.z));
            float a1 = fmaf(p.x, xs[j].y, fmaf(p.y, xv[j].y, p.z));
            s0 += ex2f(a0);
            s1 += ex2f(a1);
        }
        op[(size_t)o * HW2] = make_float2(s0, s1);
    }
}

extern "C" void kernel_launch(void* const* d_in, const int* in_sizes, int n_in,
                              void* d_out, int out_size) {
    const float* x       = (const float*)d_in[0];   // [8,8,256,256]
    const float* centers = (const float*)d_in[1];   // [16,8]
    const float* widths  = (const float*)d_in[2];   // [16,8]
    float* out = (float*)d_out;                     // [8,16,256,256]

    const int total_vec = BB * HW2;                 // 262144
    const int block = 256;
    const int grid  = total_vec / block;            // 1024
    soft_hist_kernel<<<grid, block>>>((const float2*)x, centers, widths,
                                      (float2*)out);
}